// round 16
// baseline (speedup 1.0000x reference)
#include <cuda_runtime.h>
#include <cuda_fp16.h>
#include <stdint.h>

#define NF 128
#define NMAX 10000
#define THREADS 512
#define TE 64

// ===================== scratch =====================
__device__ float g_P[NMAX * NF];
__device__ float g_Q[NMAX * NF];
__device__ int   g_is64;
// weight blob: fp16 [n][k] images, padded strides (272B big, 80B pw1)
#define WB_WC   0
#define WB_WP2  34816
#define WB_WS   69632
#define WB_WP1  104448
#define WBLOB_BYTES 114688
__device__ unsigned char g_wb[WBLOB_BYTES];

// ===================== smem map (bytes) =====================
#define SM_WC    0
#define SM_WP2   34816
#define SM_WS    69632
#define SM_PW1   104448
#define SM_AHI   114688   // a1/chem hi (64 x 272)
#define SM_ALO   132096   // a1/chem lo
#define SM_UHI   149504   // u1 hi (64 x 272)
#define SM_ULO   166912   // u1 lo
#define SM_PHI   149504   // posin hi (64 x 80) overlays UHI
#define SM_PLO   154624   // posin lo (64 x 80)
#define SM_CB1   184320
#define SM_CB2   184832
#define SM_PB1   185344
#define SM_PB2   185856
#define SM_SB    186368
#define SM_AW    186880
#define SM_ATT   187392   // 4 x 64 floats
#define SM_ROWS  188416
#define SM_COLS  188672
#define SM_AB    188928
#define SMEM_BYTES 188944

__constant__ float c_scales[15] = {
    -0.5f, -0.222222222f, -0.0987654321f, -0.0438957476f, -0.0195092212f,
    -0.00867076500f, -0.00385367333f, -0.00171274370f, -0.000761219424f,
    -0.000338319744f, -0.000150364331f, -6.68285914e-05f, -2.97015962e-05f,
    -1.32007094e-05f, -5.86698196e-06f
};

// Newton-iteration reciprocal for d in (1,2]: bit-trick seed + 2 NR steps.
// Error < 1 ulp over (1,2]; runs entirely on the FMA/ALU pipes (no MUFU.RCP).
__device__ __forceinline__ float rcp_nr(float d) {
    float r = __uint_as_float(0x7EF311C3u - __float_as_uint(d));
    r = r * (2.0f - d * r);
    r = r * (2.0f - d * r);
    return r;
}
// Stable silu: 1 MUFU (EX2) + FMA-pipe reciprocal.
__device__ __forceinline__ float siluf(float x) {
    float t = __expf(-fabsf(x));          // (0,1]
    float rd = rcp_nr(1.0f + t);          // 1/(1+t), d in (1,2]
    float sig = (x >= 0.0f) ? rd : t * rd;
    return x * sig;
}
__device__ __forceinline__ float sigmoidf(float x) {
    float t = __expf(-fabsf(x));
    float rd = rcp_nr(1.0f + t);
    return (x >= 0.0f) ? rd : t * rd;
}
// involution within 32-col blocks: swap (bits 4:3) <-> (bits 2:1)
__device__ __host__ __forceinline__ int perm32(int k) {
    return (k & ~31) | ((k << 2) & 24) | ((k >> 2) & 6) | (k & 1);
}
__device__ __forceinline__ uint32_t smem_u32(const void* p) {
    uint32_t a;
    asm("{ .reg .u64 t; cvta.to.shared.u64 t, %1; cvt.u32.u64 %0, t; }" : "=r"(a) : "l"(p));
    return a;
}
__device__ __forceinline__ void ldsm4(uint32_t addr, uint32_t* r) {
    asm volatile("ldmatrix.sync.aligned.m8n8.x4.shared.b16 {%0,%1,%2,%3}, [%4];"
        : "=r"(r[0]), "=r"(r[1]), "=r"(r[2]), "=r"(r[3]) : "r"(addr));
}
__device__ __forceinline__ void mma16816(float* c, const uint32_t* a, uint32_t b0, uint32_t b1) {
    asm volatile(
        "mma.sync.aligned.m16n8k16.row.col.f32.f16.f16.f32 "
        "{%0,%1,%2,%3},{%4,%5,%6,%7},{%8,%9},{%0,%1,%2,%3};"
        : "+f"(c[0]), "+f"(c[1]), "+f"(c[2]), "+f"(c[3])
        : "r"(a[0]), "r"(a[1]), "r"(a[2]), "r"(a[3]), "r"(b0), "r"(b1));
}
// split one f32 pair into hi fp16x2 + lo fp16x2
__device__ __forceinline__ void split2(float a, float b, __half2& hi, __half2& lo) {
    hi = __float22half2_rn(make_float2(a, b));
    lo = __float22half2_rn(make_float2(a - __low2float(hi), b - __high2float(hi)));
}

// 64xNx(16*nks) GEMM, 16 warps: warp (mw: 16 rows, nw: 32 cols).
// A hi/lo 2-pass with B fragments hoisted. acc[4][4] f32.
__device__ __forceinline__ void gemm64(
    uint32_t aHi, uint32_t aLo, uint32_t bBase, int nks,
    int mw, int nw, int lane, float acc[4][4],
    uint32_t strA, uint32_t strB)
{
    const uint32_t arow = (uint32_t)(mw * 16 + (lane & 15));
    const uint32_t brow = (uint32_t)(nw * 32 + (lane & 15));
    const uint32_t kch  = (uint32_t)(lane >> 4) * 16;
    for (int ks = 0; ks < nks; ks++) {
        const uint32_t koff = kch + ks * 32;
        uint32_t b0[4], b1[4], a[4];
        ldsm4(bBase + brow * strB + koff, b0);
        ldsm4(bBase + (brow + 16) * strB + koff, b1);
        ldsm4(aHi + arow * strA + koff, a);
        mma16816(acc[0], a, b0[0], b0[2]);
        mma16816(acc[1], a, b0[1], b0[3]);
        mma16816(acc[2], a, b1[0], b1[2]);
        mma16816(acc[3], a, b1[1], b1[3]);
        ldsm4(aLo + arow * strA + koff, a);
        mma16816(acc[0], a, b0[0], b0[2]);
        mma16816(acc[1], a, b0[1], b0[3]);
        mma16816(acc[2], a, b1[0], b1[2]);
        mma16816(acc[3], a, b1[1], b1[3]);
    }
}

// ===================== kernel 0: edge dtype detection =====================
__global__ void detect_kernel(const int* __restrict__ e32, int nprobe) {
    __shared__ int nz;
    if (threadIdx.x == 0) nz = 0;
    __syncthreads();
    int local = 0;
    for (int i = threadIdx.x; i < nprobe; i += blockDim.x)
        if (e32[2 * i + 1] != 0) local = 1;
    if (local) atomicOr(&nz, 1);
    __syncthreads();
    if (threadIdx.x == 0) g_is64 = (nz == 0) ? 1 : 0;
}

// ===================== kernel 1: fold cw1 into per-node P/Q =====================
__global__ __launch_bounds__(128) void node_pre(
    const float* __restrict__ h, const float* __restrict__ na,
    const float* __restrict__ cw1, int N)
{
    __shared__ float hs[16][128];
    __shared__ float nas[16][128];
    int n0 = blockIdx.x * 16;
    int tid = threadIdx.x;
    for (int idx = tid; idx < 16 * 128; idx += 128) {
        int n = idx >> 7, k = idx & 127;
        int gn = n0 + n;
        hs[n][k]  = (gn < N) ? h[(size_t)gn * 128 + k]  : 0.0f;
        nas[n][k] = (gn < N) ? na[(size_t)gn * 128 + k] : 0.0f;
    }
    __syncthreads();
    int j = tid;
    float accP[16], accQ[16];
#pragma unroll
    for (int n = 0; n < 16; n++) { accP[n] = 0.0f; accQ[n] = 0.0f; }
    for (int k = 0; k < 128; k++) {
        float whr = cw1[(size_t)k * 128 + j];
        float whc = cw1[(size_t)(128 + k) * 128 + j];
        float wnr = cw1[(size_t)(256 + k) * 128 + j];
        float wnc = cw1[(size_t)(384 + k) * 128 + j];
#pragma unroll
        for (int n = 0; n < 16; n++) {
            float hv = hs[n][k], nav = nas[n][k];
            accP[n] = fmaf(hv, whr, fmaf(nav, wnr, accP[n]));
            accQ[n] = fmaf(hv, whc, fmaf(nav, wnc, accQ[n]));
        }
    }
#pragma unroll
    for (int n = 0; n < 16; n++) {
        int gn = n0 + n;
        if (gn < N) {
            g_P[(size_t)gn * 128 + j] = accP[n];
            g_Q[(size_t)gn * 128 + j] = accQ[n];
        }
    }
}

// ===================== kernel 2: weight prep (transpose + fp16 + k-perm) =====================
__global__ void prep_weights(const float* __restrict__ cw2,
                             const float* __restrict__ pw2,
                             const float* __restrict__ sw,
                             const float* __restrict__ pw1)
{
    int idx = blockIdx.x * 256 + threadIdx.x;
    if (idx < 3 * 16384) {
        int m = idx / 16384, r = idx % 16384;
        int k = r >> 7, n = r & 127;
        const float* W = (m == 0) ? cw2 : ((m == 1) ? pw2 : sw);
        float w = W[(size_t)k * 128 + n];
        ((__half*)(g_wb + m * 34816))[n * 136 + perm32(k)] = __float2half_rn(w);
    } else if (idx < 3 * 16384 + 4096) {
        int r = idx - 3 * 16384;
        int k = r >> 7, n = r & 127;   // k in 0..31  (pw1: NOT permuted)
        float w = (k < 20) ? pw1[(size_t)k * 128 + n] : 0.0f;
        ((__half*)(g_wb + WB_WP1))[n * 40 + k] = __float2half_rn(w);
    }
}

// ===================== kernel 3: persistent HMMA edge kernel =====================
__global__ __launch_bounds__(THREADS) void edge_hmma_kernel(
    const float* __restrict__ coord, const float* __restrict__ nvecs,
    const float* __restrict__ cb1g,  const float* __restrict__ cb2g,
    const float* __restrict__ pb1g,  const float* __restrict__ pb2g,
    const float* __restrict__ sbg,   const float* __restrict__ awg,
    const float* __restrict__ abg,
    const void* __restrict__ edges, int E,
    float* __restrict__ out)
{
    extern __shared__ __align__(16) unsigned char smem[];
    const uint32_t sb0 = smem_u32(smem);
    const int tid = threadIdx.x;
    const int wid = tid >> 5, lane = tid & 31;
    const int mw = wid & 3;    // 16-row slice
    const int nw = wid >> 2;   // 32-col slice

    // weight blob -> smem (one-time, offsets identical)
    {
        const uint4* src = (const uint4*)g_wb;
        uint4* dst = (uint4*)smem;
        for (int i = tid; i < WBLOB_BYTES / 16; i += THREADS) dst[i] = src[i];
    }
    float* cb1s = (float*)(smem + SM_CB1);
    float* cb2s = (float*)(smem + SM_CB2);
    float* pb1s = (float*)(smem + SM_PB1);
    float* pb2s = (float*)(smem + SM_PB2);
    float* sbs  = (float*)(smem + SM_SB);
    float* aws  = (float*)(smem + SM_AW);
    float* attPs= (float*)(smem + SM_ATT);
    int*   rows = (int*)(smem + SM_ROWS);
    int*   cols = (int*)(smem + SM_COLS);
    __half* PH = (__half*)(smem + SM_PHI);
    __half* PL = (__half*)(smem + SM_PLO);
    if (tid < 128) {
        cb1s[tid] = cb1g[tid]; cb2s[tid] = cb2g[tid];
        pb1s[tid] = pb1g[tid]; pb2s[tid] = pb2g[tid];
        sbs[tid]  = sbg[tid];  aws[tid]  = awg[tid];
    }
    if (tid == 0) *(float*)(smem + SM_AB) = abg[0];
    const int is64 = g_is64;
    __syncthreads();
    const float abv = *(float*)(smem + SM_AB);

    const size_t chemO = (size_t)E * 128;
    const size_t posO  = (size_t)E * 256;
    const size_t cdO   = (size_t)E * 384;

    const int nTiles = (E + TE - 1) / TE;
    for (int t = blockIdx.x; t < nTiles; t += gridDim.x) {
        const int base = t * TE;

        // ---- Phase A: geometry -> posin hi/lo (8 threads per edge) ----
        {
            const int e = tid & 63, g = tid >> 6;   // g in 0..7
            const int ge = base + e;
            int r = 0, c = 0;
            if (ge < E) {
                if (is64) {
                    const long long* pe = (const long long*)edges;
                    r = (int)pe[ge]; c = (int)pe[(size_t)E + ge];
                } else {
                    const int* pe = (const int*)edges;
                    r = pe[ge]; c = pe[(size_t)E + ge];
                }
            }
            if (g == 0) { rows[e] = r; cols[e] = c; }
            if (g < 4) {
                float dx = coord[r * 3 + 0] - coord[c * 3 + 0];
                float dy = coord[r * 3 + 1] - coord[c * 3 + 1];
                float dz = coord[r * 3 + 2] - coord[c * 3 + 2];
                float nrm = sqrtf(dx * dx + dy * dy + dz * dz);
                float inv = __fdividef(1.0f, nrm + 1e-8f);
                float cx = dx * inv, cy = dy * inv, cz = dz * inv;
                if (g == 0 && ge < E) {
                    out[cdO + (size_t)ge * 3 + 0] = cx;
                    out[cdO + (size_t)ge * 3 + 1] = cy;
                    out[cdO + (size_t)ge * 3 + 2] = cz;
                }
                float ir = cx * cx + cy * cy + cz * cz;
#pragma unroll
                for (int s = 0; s < 4; s++) {
                    int si = g * 4 + s;
                    if (si < 15) {
                        float v = __expf(ir * c_scales[si]);
                        __half hh = __float2half_rn(v);
                        PH[e * 40 + 5 + si] = hh;
                        PL[e * 40 + 5 + si] = __float2half_rn(v - __half2float(hh));
                    }
                }
                if (g == 1) {
#pragma unroll
                    for (int k = 20; k < 32; k += 2) {
                        *(__half2*)(PH + e * 40 + k) =
                            __halves2half2(__float2half_rn(0.f), __float2half_rn(0.f));
                        *(__half2*)(PL + e * 40 + k) =
                            __halves2half2(__float2half_rn(0.f), __float2half_rn(0.f));
                    }
                }
            } else {
                int k2 = g - 4;
                for (int rep = 0; rep < 2; rep++) {
                    if (rep == 1) {
                        if (g != 4) break;
                        k2 = 4;
                    }
                    const float* av = &nvecs[((size_t)r * 5 + k2) * 3];
                    const float* bv = &nvecs[((size_t)c * 5 + k2) * 3];
                    float v = av[0] * bv[0] + av[1] * bv[1] + av[2] * bv[2];
                    __half hh = __float2half_rn(v);
                    PH[e * 40 + k2] = hh;
                    PL[e * 40 + k2] = __float2half_rn(v - __half2float(hh));
                }
            }
        }
        __syncthreads();   // S1

        // ---- Phase B: a1 = silu(P[r]+Q[c]+cb1) -> bufA hi/lo, PERMUTED, STS.128 ----
        {
            const int e = tid >> 3;
            const int k0 = (tid & 7) * 16;     // physical col base
            const int r = rows[e], c = cols[e];
            const float* Pr = g_P + (size_t)r * 128;
            const float* Qc = g_Q + (size_t)c * 128;
#pragma unroll
            for (int h16 = 0; h16 < 2; h16++) {
                const int pb = k0 + h16 * 8;       // 8 physical cols
                const int bb = pb & ~31;
                const int l3v = (pb >> 3) & 3;
                __align__(16) __half2 hi[4], lo[4];
#pragma unroll
                for (int ni = 0; ni < 4; ni++) {
                    int lk = bb + 8 * ni + 2 * l3v;   // logical col pair
                    float2 pp = *(const float2*)(Pr + lk);
                    float2 qq = *(const float2*)(Qc + lk);
                    float v0 = siluf(pp.x + qq.x + cb1s[lk]);
                    float v1 = siluf(pp.y + qq.y + cb1s[lk + 1]);
                    split2(v0, v1, hi[ni], lo[ni]);
                }
                *(uint4*)(smem + SM_AHI + e * 272 + pb * 2) = *(uint4*)hi;
                *(uint4*)(smem + SM_ALO + e * 272 + pb * 2) = *(uint4*)lo;
            }
        }
        __syncthreads();   // S2

        // ---- GEMM1: u1_pre = posin @ pw1 ; chem_pre = a1 @ cw2 ----
        float accU[4][4], accC[4][4];
#pragma unroll
        for (int b = 0; b < 4; b++)
#pragma unroll
            for (int q = 0; q < 4; q++) { accU[b][q] = 0.0f; accC[b][q] = 0.0f; }
        gemm64(sb0 + SM_PHI, sb0 + SM_PLO, sb0 + SM_PW1, 2, mw, nw, lane, accU, 80, 80);
        gemm64(sb0 + SM_AHI, sb0 + SM_ALO, sb0 + SM_WC, 8, mw, nw, lane, accC, 272, 272);
        __syncthreads();   // S3

        // ---- Epilogue A: chem -> gmem + bufA (perm, STS.128); u1 -> bufU ----
        {
            const int l3 = lane & 3;
            const int rrow = mw * 16 + (lane >> 2);
            const uint32_t physo = (uint32_t)(nw * 32 + l3 * 8) * 2;
            __align__(16) __half2 ch0[4], cl0[4], ch1[4], cl1[4];
            __align__(16) __half2 uh0[4], ul0[4], uh1[4], ul1[4];
#pragma unroll
            for (int ni = 0; ni < 4; ni++) {
                int cc = nw * 32 + ni * 8 + 2 * l3;
                float v00 = siluf(accC[ni][0] + cb2s[cc]);
                float v01 = siluf(accC[ni][1] + cb2s[cc + 1]);
                float v10 = siluf(accC[ni][2] + cb2s[cc]);
                float v11 = siluf(accC[ni][3] + cb2s[cc + 1]);
                int ge0 = base + rrow, ge1 = base + rrow + 8;
                if (ge0 < E) *(float2*)(out + chemO + (size_t)ge0 * 128 + cc) = make_float2(v00, v01);
                if (ge1 < E) *(float2*)(out + chemO + (size_t)ge1 * 128 + cc) = make_float2(v10, v11);
                split2(v00, v01, ch0[ni], cl0[ni]);
                split2(v10, v11, ch1[ni], cl1[ni]);
                float u00 = siluf(accU[ni][0] + pb1s[cc]);
                float u01 = siluf(accU[ni][1] + pb1s[cc + 1]);
                float u10 = siluf(accU[ni][2] + pb1s[cc]);
                float u11 = siluf(accU[ni][3] + pb1s[cc + 1]);
                split2(u00, u01, uh0[ni], ul0[ni]);
                split2(u10, u11, uh1[ni], ul1[ni]);
            }
            *(uint4*)(smem + SM_AHI + rrow * 272 + physo)       = *(uint4*)ch0;
            *(uint4*)(smem + SM_AHI + (rrow + 8) * 272 + physo) = *(uint4*)ch1;
            *(uint4*)(smem + SM_ALO + rrow * 272 + physo)       = *(uint4*)cl0;
            *(uint4*)(smem + SM_ALO + (rrow + 8) * 272 + physo) = *(uint4*)cl1;
            *(uint4*)(smem + SM_UHI + rrow * 272 + physo)       = *(uint4*)uh0;
            *(uint4*)(smem + SM_UHI + (rrow + 8) * 272 + physo) = *(uint4*)uh1;
            *(uint4*)(smem + SM_ULO + rrow * 272 + physo)       = *(uint4*)ul0;
            *(uint4*)(smem + SM_ULO + (rrow + 8) * 272 + physo) = *(uint4*)ul1;
        }
        __syncthreads();   // S4

        // ---- GEMM2: pos_pre = u1 @ pw2 ; gate_pre = chem @ sw ----
        float accP4[4][4], accG[4][4];
#pragma unroll
        for (int b = 0; b < 4; b++)
#pragma unroll
            for (int q = 0; q < 4; q++) { accP4[b][q] = 0.0f; accG[b][q] = 0.0f; }
        gemm64(sb0 + SM_UHI, sb0 + SM_ULO, sb0 + SM_WP2, 8, mw, nw, lane, accP4, 272, 272);
        gemm64(sb0 + SM_AHI, sb0 + SM_ALO, sb0 + SM_WS, 8, mw, nw, lane, accG, 272, 272);

        // ---- Epilogue B part 1: pos -> gmem; gate*pos; att partials ----
        float rs0 = 0.0f, rs1 = 0.0f;
#pragma unroll
        for (int ni = 0; ni < 4; ni++) {
            float* cp_ = accP4[ni];
            float* cg = accG[ni];
            int rrow = mw * 16 + (lane >> 2);
            int cc = nw * 32 + ni * 8 + 2 * (lane & 3);
            float p00 = siluf(cp_[0] + pb2s[cc]);
            float p01 = siluf(cp_[1] + pb2s[cc + 1]);
            float p10 = siluf(cp_[2] + pb2s[cc]);
            float p11 = siluf(cp_[3] + pb2s[cc + 1]);
            int ge0 = base + rrow, ge1 = base + rrow + 8;
            if (ge0 < E) *(float2*)(out + posO + (size_t)ge0 * 128 + cc) = make_float2(p00, p01);
            if (ge1 < E) *(float2*)(out + posO + (size_t)ge1 * 128 + cc) = make_float2(p10, p11);
            float g00 = siluf(cg[0] + sbs[cc])     * p00;
            float g01 = siluf(cg[1] + sbs[cc + 1]) * p01;
            float g10 = siluf(cg[2] + sbs[cc])     * p10;
            float g11 = siluf(cg[3] + sbs[cc + 1]) * p11;
            cg[0] = g00; cg[1] = g01; cg[2] = g10; cg[3] = g11;
            rs0 += g00 * aws[cc] + g01 * aws[cc + 1];
            rs1 += g10 * aws[cc] + g11 * aws[cc + 1];
        }
        rs0 += __shfl_xor_sync(0xffffffffu, rs0, 1);
        rs0 += __shfl_xor_sync(0xffffffffu, rs0, 2);
        rs1 += __shfl_xor_sync(0xffffffffu, rs1, 1);
        rs1 += __shfl_xor_sync(0xffffffffu, rs1, 2);
        if ((lane & 3) == 0) {
            int row = mw * 16 + (lane >> 2);
            attPs[nw * 64 + row] = rs0;
            attPs[nw * 64 + row + 8] = rs1;
        }
        __syncthreads();   // S5

        // ---- Epilogue B part 2: att; final store ----
        int row0 = mw * 16 + (lane >> 2);
        float att0 = sigmoidf(attPs[row0] + attPs[64 + row0] +
                              attPs[128 + row0] + attPs[192 + row0] + abv);
        float att1 = sigmoidf(attPs[row0 + 8] + attPs[64 + row0 + 8] +
                              attPs[128 + row0 + 8] + attPs[192 + row0 + 8] + abv);
#pragma unroll
        for (int ni = 0; ni < 4; ni++) {
            float* cg = accG[ni];
            int cc = nw * 32 + ni * 8 + 2 * (lane & 3);
            int ge0 = base + row0, ge1 = base + row0 + 8;
            if (ge0 < E) *(float2*)(out + (size_t)ge0 * 128 + cc) =
                make_float2(cg[0] * att0, cg[1] * att0);
            if (ge1 < E) *(float2*)(out + (size_t)ge1 * 128 + cc) =
                make_float2(cg[2] * att1, cg[3] * att1);
        }
        __syncthreads();   // S6
    }
}

// ===================== launch =====================
extern "C" void kernel_launch(void* const* d_in, const int* in_sizes, int n_in,
                              void* d_out, int out_size) {
    const float* h     = (const float*)d_in[0];
    const float* coord = (const float*)d_in[1];
    const float* nvecs = (const float*)d_in[2];
    const float* na    = (const float*)d_in[3];
    const float* cw1   = (const float*)d_in[4];
    const float* cb1   = (const float*)d_in[5];
    const float* cw2   = (const float*)d_in[6];
    const float* cb2   = (const float*)d_in[7];
    const float* pw1   = (const float*)d_in[8];
    const float* pb1   = (const float*)d_in[9];
    const float* pw2   = (const float*)d_in[10];
    const float* pb2   = (const float*)d_in[11];
    const float* sw    = (const float*)d_in[12];
    const float* sb    = (const float*)d_in[13];
    const float* aw    = (const float*)d_in[14];
    const float* ab    = (const float*)d_in[15];
    const void*  edges = d_in[16];

    const int N = in_sizes[0] / NF;
    const int E = out_size / 387;   // out, chem, pos (128 each) + cd (3)
    float* out = (float*)d_out;

    cudaFuncSetAttribute(edge_hmma_kernel,
                         cudaFuncAttributeMaxDynamicSharedMemorySize, SMEM_BYTES);

    int nprobe = (E < 1024) ? E : 1024;
    detect_kernel<<<1, 256>>>((const int*)edges, nprobe);
    prep_weights<<<(3 * 16384 + 4096 + 255) / 256, 256>>>(cw2, pw2, sw, pw1);
    node_pre<<<(N + 15) / 16, 128>>>(h, na, cw1, N);

    const int nTiles = (E + TE - 1) / TE;
    const int grid = nTiles < 148 ? nTiles : 148;
    edge_hmma_kernel<<<grid, THREADS, SMEM_BYTES>>>(
        coord, nvecs, cb1, cb2, pb1, pb2, sb, aw, ab, edges, E, out);
}

// round 17
// speedup vs baseline: 1.0362x; 1.0362x over previous
#include <cuda_runtime.h>
#include <cuda_fp16.h>
#include <stdint.h>

#define NF 128
#define NMAX 10000
#define THREADS 512
#define TE 64

// ===================== scratch =====================
__device__ float g_P[NMAX * NF];
__device__ float g_Q[NMAX * NF];
__device__ int   g_is64;
// weight blob: fp16 [n][k] images, padded strides (272B big, 80B pw1)
#define WB_WC   0
#define WB_WP2  34816
#define WB_WS   69632
#define WB_WP1  104448
#define WBLOB_BYTES 114688
__device__ unsigned char g_wb[WBLOB_BYTES];

// ===================== smem map (bytes) =====================
#define SM_WC    0
#define SM_WP2   34816
#define SM_WS    69632
#define SM_PW1   104448
#define SM_AHI   114688   // a1/chem hi (64 x 272)
#define SM_ALO   132096   // a1/chem lo
#define SM_UHI   149504   // u1 hi (64 x 272)
#define SM_ULO   166912   // u1 lo
#define SM_PHI   149504   // posin hi (64 x 80) overlays UHI
#define SM_PLO   154624   // posin lo (64 x 80)
#define SM_CB1   184320
#define SM_CB2   184832
#define SM_PB1   185344
#define SM_PB2   185856
#define SM_SB    186368
#define SM_AW    186880
#define SM_ATT   187392   // 4 x 64 floats
#define SM_AB    188928
#define SMEM_BYTES 188944

__constant__ float c_scales[15] = {
    -0.5f, -0.222222222f, -0.0987654321f, -0.0438957476f, -0.0195092212f,
    -0.00867076500f, -0.00385367333f, -0.00171274370f, -0.000761219424f,
    -0.000338319744f, -0.000150364331f, -6.68285914e-05f, -2.97015962e-05f,
    -1.32007094e-05f, -5.86698196e-06f
};

__device__ __forceinline__ float siluf(float x) {
    return __fdividef(x, 1.0f + __expf(-x));
}
__device__ __forceinline__ float sigmoidf(float x) {
    return __fdividef(1.0f, 1.0f + __expf(-x));
}
// involution within 32-col blocks: swap (bits 4:3) <-> (bits 2:1)
__device__ __host__ __forceinline__ int perm32(int k) {
    return (k & ~31) | ((k << 2) & 24) | ((k >> 2) & 6) | (k & 1);
}
__device__ __forceinline__ uint32_t smem_u32(const void* p) {
    uint32_t a;
    asm("{ .reg .u64 t; cvta.to.shared.u64 t, %1; cvt.u32.u64 %0, t; }" : "=r"(a) : "l"(p));
    return a;
}
__device__ __forceinline__ void ldsm4(uint32_t addr, uint32_t* r) {
    asm volatile("ldmatrix.sync.aligned.m8n8.x4.shared.b16 {%0,%1,%2,%3}, [%4];"
        : "=r"(r[0]), "=r"(r[1]), "=r"(r[2]), "=r"(r[3]) : "r"(addr));
}
__device__ __forceinline__ void mma16816(float* c, const uint32_t* a, uint32_t b0, uint32_t b1) {
    asm volatile(
        "mma.sync.aligned.m16n8k16.row.col.f32.f16.f16.f32 "
        "{%0,%1,%2,%3},{%4,%5,%6,%7},{%8,%9},{%0,%1,%2,%3};"
        : "+f"(c[0]), "+f"(c[1]), "+f"(c[2]), "+f"(c[3])
        : "r"(a[0]), "r"(a[1]), "r"(a[2]), "r"(a[3]), "r"(b0), "r"(b1));
}
// split one f32 pair into hi fp16x2 + lo fp16x2
__device__ __forceinline__ void split2(float a, float b, __half2& hi, __half2& lo) {
    hi = __float22half2_rn(make_float2(a, b));
    lo = __float22half2_rn(make_float2(a - __low2float(hi), b - __high2float(hi)));
}

// 64xNx(16*nks) GEMM, 16 warps: warp (mw: 16 rows, nw: 32 cols).
// A hi/lo 2-pass with B fragments hoisted. acc[4][4] f32.
__device__ __forceinline__ void gemm64(
    uint32_t aHi, uint32_t aLo, uint32_t bBase, int nks,
    int mw, int nw, int lane, float acc[4][4],
    uint32_t strA, uint32_t strB)
{
    const uint32_t arow = (uint32_t)(mw * 16 + (lane & 15));
    const uint32_t brow = (uint32_t)(nw * 32 + (lane & 15));
    const uint32_t kch  = (uint32_t)(lane >> 4) * 16;
    for (int ks = 0; ks < nks; ks++) {
        const uint32_t koff = kch + ks * 32;
        uint32_t b0[4], b1[4], a[4];
        ldsm4(bBase + brow * strB + koff, b0);
        ldsm4(bBase + (brow + 16) * strB + koff, b1);
        ldsm4(aHi + arow * strA + koff, a);
        mma16816(acc[0], a, b0[0], b0[2]);
        mma16816(acc[1], a, b0[1], b0[3]);
        mma16816(acc[2], a, b1[0], b1[2]);
        mma16816(acc[3], a, b1[1], b1[3]);
        ldsm4(aLo + arow * strA + koff, a);
        mma16816(acc[0], a, b0[0], b0[2]);
        mma16816(acc[1], a, b0[1], b0[3]);
        mma16816(acc[2], a, b1[0], b1[2]);
        mma16816(acc[3], a, b1[1], b1[3]);
    }
}

// ===================== kernel 0: edge dtype detection =====================
__global__ void detect_kernel(const int* __restrict__ e32, int nprobe) {
    __shared__ int nz;
    if (threadIdx.x == 0) nz = 0;
    __syncthreads();
    int local = 0;
    for (int i = threadIdx.x; i < nprobe; i += blockDim.x)
        if (e32[2 * i + 1] != 0) local = 1;
    if (local) atomicOr(&nz, 1);
    __syncthreads();
    if (threadIdx.x == 0) g_is64 = (nz == 0) ? 1 : 0;
}

// ===================== kernel 1: fold cw1 into per-node P/Q =====================
__global__ __launch_bounds__(128) void node_pre(
    const float* __restrict__ h, const float* __restrict__ na,
    const float* __restrict__ cw1, int N)
{
    __shared__ float hs[16][128];
    __shared__ float nas[16][128];
    int n0 = blockIdx.x * 16;
    int tid = threadIdx.x;
    for (int idx = tid; idx < 16 * 128; idx += 128) {
        int n = idx >> 7, k = idx & 127;
        int gn = n0 + n;
        hs[n][k]  = (gn < N) ? h[(size_t)gn * 128 + k]  : 0.0f;
        nas[n][k] = (gn < N) ? na[(size_t)gn * 128 + k] : 0.0f;
    }
    __syncthreads();
    int j = tid;
    float accP[16], accQ[16];
#pragma unroll
    for (int n = 0; n < 16; n++) { accP[n] = 0.0f; accQ[n] = 0.0f; }
    for (int k = 0; k < 128; k++) {
        float whr = cw1[(size_t)k * 128 + j];
        float whc = cw1[(size_t)(128 + k) * 128 + j];
        float wnr = cw1[(size_t)(256 + k) * 128 + j];
        float wnc = cw1[(size_t)(384 + k) * 128 + j];
#pragma unroll
        for (int n = 0; n < 16; n++) {
            float hv = hs[n][k], nav = nas[n][k];
            accP[n] = fmaf(hv, whr, fmaf(nav, wnr, accP[n]));
            accQ[n] = fmaf(hv, whc, fmaf(nav, wnc, accQ[n]));
        }
    }
#pragma unroll
    for (int n = 0; n < 16; n++) {
        int gn = n0 + n;
        if (gn < N) {
            g_P[(size_t)gn * 128 + j] = accP[n];
            g_Q[(size_t)gn * 128 + j] = accQ[n];
        }
    }
}

// ===================== kernel 2: weight prep (transpose + fp16 + k-perm) =====================
__global__ void prep_weights(const float* __restrict__ cw2,
                             const float* __restrict__ pw2,
                             const float* __restrict__ sw,
                             const float* __restrict__ pw1)
{
    int idx = blockIdx.x * 256 + threadIdx.x;
    if (idx < 3 * 16384) {
        int m = idx / 16384, r = idx % 16384;
        int k = r >> 7, n = r & 127;
        const float* W = (m == 0) ? cw2 : ((m == 1) ? pw2 : sw);
        float w = W[(size_t)k * 128 + n];
        ((__half*)(g_wb + m * 34816))[n * 136 + perm32(k)] = __float2half_rn(w);
    } else if (idx < 3 * 16384 + 4096) {
        int r = idx - 3 * 16384;
        int k = r >> 7, n = r & 127;   // k in 0..31  (pw1: NOT permuted)
        float w = (k < 20) ? pw1[(size_t)k * 128 + n] : 0.0f;
        ((__half*)(g_wb + WB_WP1))[n * 40 + k] = __float2half_rn(w);
    }
}

// edge index load helper
__device__ __forceinline__ void load_edge(const void* edges, int is64, int E,
                                          int ge, int& r, int& c) {
    r = 0; c = 0;
    if (ge < E) {
        if (is64) {
            const long long* pe = (const long long*)edges;
            r = (int)pe[ge]; c = (int)pe[(size_t)E + ge];
        } else {
            const int* pe = (const int*)edges;
            r = pe[ge]; c = pe[(size_t)E + ge];
        }
    }
}

// ===================== kernel 3: persistent HMMA edge kernel =====================
__global__ __launch_bounds__(THREADS) void edge_hmma_kernel(
    const float* __restrict__ coord, const float* __restrict__ nvecs,
    const float* __restrict__ cb1g,  const float* __restrict__ cb2g,
    const float* __restrict__ pb1g,  const float* __restrict__ pb2g,
    const float* __restrict__ sbg,   const float* __restrict__ awg,
    const float* __restrict__ abg,
    const void* __restrict__ edges, int E,
    float* __restrict__ out)
{
    extern __shared__ __align__(16) unsigned char smem[];
    const uint32_t sb0 = smem_u32(smem);
    const int tid = threadIdx.x;
    const int wid = tid >> 5, lane = tid & 31;
    const int mw = wid & 3;    // 16-row slice
    const int nw = wid >> 2;   // 32-col slice
    const int eB = tid >> 3;           // Phase-B edge within tile
    const int k0B = (tid & 7) * 16;    // Phase-B physical col base

    // weight blob -> smem (one-time, offsets identical)
    {
        const uint4* src = (const uint4*)g_wb;
        uint4* dst = (uint4*)smem;
        for (int i = tid; i < WBLOB_BYTES / 16; i += THREADS) dst[i] = src[i];
    }
    float* cb1s = (float*)(smem + SM_CB1);
    float* cb2s = (float*)(smem + SM_CB2);
    float* pb1s = (float*)(smem + SM_PB1);
    float* pb2s = (float*)(smem + SM_PB2);
    float* sbs  = (float*)(smem + SM_SB);
    float* aws  = (float*)(smem + SM_AW);
    float* attPs= (float*)(smem + SM_ATT);
    __half* PH = (__half*)(smem + SM_PHI);
    __half* PL = (__half*)(smem + SM_PLO);
    if (tid < 128) {
        cb1s[tid] = cb1g[tid]; cb2s[tid] = cb2g[tid];
        pb1s[tid] = pb1g[tid]; pb2s[tid] = pb2g[tid];
        sbs[tid]  = sbg[tid];  aws[tid]  = awg[tid];
    }
    if (tid == 0) *(float*)(smem + SM_AB) = abg[0];
    const int is64 = g_is64;
    __syncthreads();
    const float abv = *(float*)(smem + SM_AB);

    const size_t chemO = (size_t)E * 128;
    const size_t posO  = (size_t)E * 256;
    const size_t cdO   = (size_t)E * 384;

    const int nTiles = (E + TE - 1) / TE;

    // ---- prologue: prefetch P rows + indices for first tile ----
    int cB = 0;
    float2 pfP[8];
    {
        int t0 = blockIdx.x;
        if (t0 < nTiles) {
            int r;
            load_edge(edges, is64, E, t0 * TE + eB, r, cB);
            const float* Pr = g_P + (size_t)r * 128;
#pragma unroll
            for (int h16 = 0; h16 < 2; h16++) {
                const int pb = k0B + h16 * 8;
                const int bb = pb & ~31;
                const int l3v = (pb >> 3) & 3;
#pragma unroll
                for (int ni = 0; ni < 4; ni++)
                    pfP[h16 * 4 + ni] = *(const float2*)(Pr + bb + 8 * ni + 2 * l3v);
            }
        }
    }

    for (int t = blockIdx.x; t < nTiles; t += gridDim.x) {
        const int base = t * TE;

        // ---- Phase AB: Q gather + geometry/posin + a1 staging ----
        {
            // Q loads first (latency hidden behind geometry work below)
            float2 qv[8];
            {
                const float* Qc = g_Q + (size_t)cB * 128;
#pragma unroll
                for (int h16 = 0; h16 < 2; h16++) {
                    const int pb = k0B + h16 * 8;
                    const int bb = pb & ~31;
                    const int l3v = (pb >> 3) & 3;
#pragma unroll
                    for (int ni = 0; ni < 4; ni++)
                        qv[h16 * 4 + ni] = *(const float2*)(Qc + bb + 8 * ni + 2 * l3v);
                }
            }
            // geometry role (self-loaded indices): eA = tid & 63, g = tid >> 6
            {
                const int eA = tid & 63, g = tid >> 6;   // g in 0..7
                const int geA = base + eA;
                int rA, cA;
                load_edge(edges, is64, E, geA, rA, cA);
                if (g < 4) {
                    float dx = coord[rA * 3 + 0] - coord[cA * 3 + 0];
                    float dy = coord[rA * 3 + 1] - coord[cA * 3 + 1];
                    float dz = coord[rA * 3 + 2] - coord[cA * 3 + 2];
                    float nrm = sqrtf(dx * dx + dy * dy + dz * dz);
                    float inv = __fdividef(1.0f, nrm + 1e-8f);
                    float cx = dx * inv, cy = dy * inv, cz = dz * inv;
                    if (g == 0 && geA < E) {
                        out[cdO + (size_t)geA * 3 + 0] = cx;
                        out[cdO + (size_t)geA * 3 + 1] = cy;
                        out[cdO + (size_t)geA * 3 + 2] = cz;
                    }
                    float ir = cx * cx + cy * cy + cz * cz;
#pragma unroll
                    for (int s = 0; s < 4; s++) {
                        int si = g * 4 + s;
                        if (si < 15) {
                            float v = __expf(ir * c_scales[si]);
                            __half hh = __float2half_rn(v);
                            PH[eA * 40 + 5 + si] = hh;
                            PL[eA * 40 + 5 + si] = __float2half_rn(v - __half2float(hh));
                        }
                    }
                    if (g == 1) {
#pragma unroll
                        for (int k = 20; k < 32; k += 2) {
                            *(__half2*)(PH + eA * 40 + k) =
                                __halves2half2(__float2half_rn(0.f), __float2half_rn(0.f));
                            *(__half2*)(PL + eA * 40 + k) =
                                __halves2half2(__float2half_rn(0.f), __float2half_rn(0.f));
                        }
                    }
                } else {
                    int k2 = g - 4;
                    for (int rep = 0; rep < 2; rep++) {
                        if (rep == 1) {
                            if (g != 4) break;
                            k2 = 4;
                        }
                        const float* av = &nvecs[((size_t)rA * 5 + k2) * 3];
                        const float* bv = &nvecs[((size_t)cA * 5 + k2) * 3];
                        float v = av[0] * bv[0] + av[1] * bv[1] + av[2] * bv[2];
                        __half hh = __float2half_rn(v);
                        PH[eA * 40 + k2] = hh;
                        PL[eA * 40 + k2] = __float2half_rn(v - __half2float(hh));
                    }
                }
            }
            // combine P(prefetched) + Q + cb1 -> silu -> STS.128 (perm layout)
#pragma unroll
            for (int h16 = 0; h16 < 2; h16++) {
                const int pb = k0B + h16 * 8;
                const int bb = pb & ~31;
                const int l3v = (pb >> 3) & 3;
                __align__(16) __half2 hi[4], lo[4];
#pragma unroll
                for (int ni = 0; ni < 4; ni++) {
                    int lk = bb + 8 * ni + 2 * l3v;
                    float2 pp = pfP[h16 * 4 + ni];
                    float2 qq = qv[h16 * 4 + ni];
                    float v0 = siluf(pp.x + qq.x + cb1s[lk]);
                    float v1 = siluf(pp.y + qq.y + cb1s[lk + 1]);
                    split2(v0, v1, hi[ni], lo[ni]);
                }
                *(uint4*)(smem + SM_AHI + eB * 272 + pb * 2) = *(uint4*)hi;
                *(uint4*)(smem + SM_ALO + eB * 272 + pb * 2) = *(uint4*)lo;
            }
        }
        __syncthreads();   // S1

        // ---- GEMM1: u1_pre = posin @ pw1 ; chem_pre = a1 @ cw2 ----
        float accU[4][4], accC[4][4];
#pragma unroll
        for (int b = 0; b < 4; b++)
#pragma unroll
            for (int q = 0; q < 4; q++) { accU[b][q] = 0.0f; accC[b][q] = 0.0f; }
        gemm64(sb0 + SM_PHI, sb0 + SM_PLO, sb0 + SM_PW1, 2, mw, nw, lane, accU, 80, 80);
        gemm64(sb0 + SM_AHI, sb0 + SM_ALO, sb0 + SM_WC, 8, mw, nw, lane, accC, 272, 272);
        __syncthreads();   // S2

        // ---- Epilogue A: chem -> gmem + bufA (perm, STS.128); u1 -> bufU ----
        {
            const int l3 = lane & 3;
            const int rrow = mw * 16 + (lane >> 2);
            const uint32_t physo = (uint32_t)(nw * 32 + l3 * 8) * 2;
            __align__(16) __half2 ch0[4], cl0[4], ch1[4], cl1[4];
            __align__(16) __half2 uh0[4], ul0[4], uh1[4], ul1[4];
#pragma unroll
            for (int ni = 0; ni < 4; ni++) {
                int cc = nw * 32 + ni * 8 + 2 * l3;
                float v00 = siluf(accC[ni][0] + cb2s[cc]);
                float v01 = siluf(accC[ni][1] + cb2s[cc + 1]);
                float v10 = siluf(accC[ni][2] + cb2s[cc]);
                float v11 = siluf(accC[ni][3] + cb2s[cc + 1]);
                int ge0 = base + rrow, ge1 = base + rrow + 8;
                if (ge0 < E) *(float2*)(out + chemO + (size_t)ge0 * 128 + cc) = make_float2(v00, v01);
                if (ge1 < E) *(float2*)(out + chemO + (size_t)ge1 * 128 + cc) = make_float2(v10, v11);
                split2(v00, v01, ch0[ni], cl0[ni]);
                split2(v10, v11, ch1[ni], cl1[ni]);
                float u00 = siluf(accU[ni][0] + pb1s[cc]);
                float u01 = siluf(accU[ni][1] + pb1s[cc + 1]);
                float u10 = siluf(accU[ni][2] + pb1s[cc]);
                float u11 = siluf(accU[ni][3] + pb1s[cc + 1]);
                split2(u00, u01, uh0[ni], ul0[ni]);
                split2(u10, u11, uh1[ni], ul1[ni]);
            }
            *(uint4*)(smem + SM_AHI + rrow * 272 + physo)       = *(uint4*)ch0;
            *(uint4*)(smem + SM_AHI + (rrow + 8) * 272 + physo) = *(uint4*)ch1;
            *(uint4*)(smem + SM_ALO + rrow * 272 + physo)       = *(uint4*)cl0;
            *(uint4*)(smem + SM_ALO + (rrow + 8) * 272 + physo) = *(uint4*)cl1;
            *(uint4*)(smem + SM_UHI + rrow * 272 + physo)       = *(uint4*)uh0;
            *(uint4*)(smem + SM_UHI + (rrow + 8) * 272 + physo) = *(uint4*)uh1;
            *(uint4*)(smem + SM_ULO + rrow * 272 + physo)       = *(uint4*)ul0;
            *(uint4*)(smem + SM_ULO + (rrow + 8) * 272 + physo) = *(uint4*)ul1;
        }
        __syncthreads();   // S3

        // ---- prefetch next tile's P rows + indices (hidden behind GEMM2) ----
        {
            int tn = t + gridDim.x;
            if (tn < nTiles) {
                int r;
                load_edge(edges, is64, E, tn * TE + eB, r, cB);
                const float* Pr = g_P + (size_t)r * 128;
#pragma unroll
                for (int h16 = 0; h16 < 2; h16++) {
                    const int pb = k0B + h16 * 8;
                    const int bb = pb & ~31;
                    const int l3v = (pb >> 3) & 3;
#pragma unroll
                    for (int ni = 0; ni < 4; ni++)
                        pfP[h16 * 4 + ni] = *(const float2*)(Pr + bb + 8 * ni + 2 * l3v);
                }
            }
        }

        // ---- GEMM2: pos_pre = u1 @ pw2 ; gate_pre = chem @ sw ----
        float accP4[4][4], accG[4][4];
#pragma unroll
        for (int b = 0; b < 4; b++)
#pragma unroll
            for (int q = 0; q < 4; q++) { accP4[b][q] = 0.0f; accG[b][q] = 0.0f; }
        gemm64(sb0 + SM_UHI, sb0 + SM_ULO, sb0 + SM_WP2, 8, mw, nw, lane, accP4, 272, 272);
        gemm64(sb0 + SM_AHI, sb0 + SM_ALO, sb0 + SM_WS, 8, mw, nw, lane, accG, 272, 272);

        // ---- Epilogue B part 1: pos -> gmem; gate*pos; att partials ----
        float rs0 = 0.0f, rs1 = 0.0f;
#pragma unroll
        for (int ni = 0; ni < 4; ni++) {
            float* cp_ = accP4[ni];
            float* cg = accG[ni];
            int rrow = mw * 16 + (lane >> 2);
            int cc = nw * 32 + ni * 8 + 2 * (lane & 3);
            float p00 = siluf(cp_[0] + pb2s[cc]);
            float p01 = siluf(cp_[1] + pb2s[cc + 1]);
            float p10 = siluf(cp_[2] + pb2s[cc]);
            float p11 = siluf(cp_[3] + pb2s[cc + 1]);
            int ge0 = base + rrow, ge1 = base + rrow + 8;
            if (ge0 < E) *(float2*)(out + posO + (size_t)ge0 * 128 + cc) = make_float2(p00, p01);
            if (ge1 < E) *(float2*)(out + posO + (size_t)ge1 * 128 + cc) = make_float2(p10, p11);
            float g00 = siluf(cg[0] + sbs[cc])     * p00;
            float g01 = siluf(cg[1] + sbs[cc + 1]) * p01;
            float g10 = siluf(cg[2] + sbs[cc])     * p10;
            float g11 = siluf(cg[3] + sbs[cc + 1]) * p11;
            cg[0] = g00; cg[1] = g01; cg[2] = g10; cg[3] = g11;
            rs0 += g00 * aws[cc] + g01 * aws[cc + 1];
            rs1 += g10 * aws[cc] + g11 * aws[cc + 1];
        }
        rs0 += __shfl_xor_sync(0xffffffffu, rs0, 1);
        rs0 += __shfl_xor_sync(0xffffffffu, rs0, 2);
        rs1 += __shfl_xor_sync(0xffffffffu, rs1, 1);
        rs1 += __shfl_xor_sync(0xffffffffu, rs1, 2);
        if ((lane & 3) == 0) {
            int row = mw * 16 + (lane >> 2);
            attPs[nw * 64 + row] = rs0;
            attPs[nw * 64 + row + 8] = rs1;
        }
        __syncthreads();   // S4

        // ---- Epilogue B part 2: att; final store ----
        int row0 = mw * 16 + (lane >> 2);
        float att0 = sigmoidf(attPs[row0] + attPs[64 + row0] +
                              attPs[128 + row0] + attPs[192 + row0] + abv);
        float att1 = sigmoidf(attPs[row0 + 8] + attPs[64 + row0 + 8] +
                              attPs[128 + row0 + 8] + attPs[192 + row0 + 8] + abv);
#pragma unroll
        for (int ni = 0; ni < 4; ni++) {
            float* cg = accG[ni];
            int cc = nw * 32 + ni * 8 + 2 * (lane & 3);
            int ge0 = base + row0, ge1 = base + row0 + 8;
            if (ge0 < E) *(float2*)(out + (size_t)ge0 * 128 + cc) =
                make_float2(cg[0] * att0, cg[1] * att0);
            if (ge1 < E) *(float2*)(out + (size_t)ge1 * 128 + cc) =
                make_float2(cg[2] * att1, cg[3] * att1);
        }
        // no end-of-tile barrier: next Phase AB's smem writes are ordered by
        // S4 (GEMM2/EpiB readers done) and cannot outrun EpiB2 (S1..S3 fence).
    }
}

// ===================== launch =====================
extern "C" void kernel_launch(void* const* d_in, const int* in_sizes, int n_in,
                              void* d_out, int out_size) {
    const float* h     = (const float*)d_in[0];
    const float* coord = (const float*)d_in[1];
    const float* nvecs = (const float*)d_in[2];
    const float* na    = (const float*)d_in[3];
    const float* cw1   = (const float*)d_in[4];
    const float* cb1   = (const float*)d_in[5];
    const float* cw2   = (const float*)d_in[6];
    const float* cb2   = (const float*)d_in[7];
    const float* pw1   = (const float*)d_in[8];
    const float* pb1   = (const float*)d_in[9];
    const float* pw2   = (const float*)d_in[10];
    const float* pb2   = (const float*)d_in[11];
    const float* sw    = (const float*)d_in[12];
    const float* sb    = (const float*)d_in[13];
    const float* aw    = (const float*)d_in[14];
    const float* ab    = (const float*)d_in[15];
    const void*  edges = d_in[16];

    const int N = in_sizes[0] / NF;
    const int E = out_size / 387;   // out, chem, pos (128 each) + cd (3)
    float* out = (float*)d_out;

    cudaFuncSetAttribute(edge_hmma_kernel,
                         cudaFuncAttributeMaxDynamicSharedMemorySize, SMEM_BYTES);

    int nprobe = (E < 1024) ? E : 1024;
    detect_kernel<<<1, 256>>>((const int*)edges, nprobe);
    prep_weights<<<(3 * 16384 + 4096 + 255) / 256, 256>>>(cw2, pw2, sw, pw1);
    node_pre<<<(N + 15) / 16, 128>>>(h, na, cw1, N);

    const int nTiles = (E + TE - 1) / TE;
    const int grid = nTiles < 148 ? nTiles : 148;
    edge_hmma_kernel<<<grid, THREADS, SMEM_BYTES>>>(
        coord, nvecs, cb1, cb2, pb1, pb2, sb, aw, ab, edges, E, out);
}